// round 2
// baseline (speedup 1.0000x reference)
#include <cuda_runtime.h>

// ---------------------------------------------------------------------------
// OctreeInterp: trilinear interpolation over a sparse octree (depth=8).
//   For each query point: 8 corner Morton keys -> lower_bound in sorted
//   node_keys -> gather 32-ch features for found corners -> weighted sum /
//   sum of valid weights.
//
// Acceleration structure: bucket table over the 2^26 key space.
//   table[t] = lower_bound(node_keys, t << SHIFT), 2^22 buckets (SHIFT=4).
//   Avg bucket occupancy = 2M / 4.2M = 0.5, so most searches finish with just
//   the two table loads (lo==hi => key absent; pos==hi => key absent since
//   node_keys[pos] >= (t+1)<<SHIFT > key).
// ---------------------------------------------------------------------------

#define DEPTH      8
#define KEY_BITS   26               // 2 batch bits + 3*DEPTH morton bits
#define NB_LOG     22
#define NB         (1 << NB_LOG)    // 4,194,304 buckets
#define SHIFT      (KEY_BITS - NB_LOG)  // 4

__device__ int g_table[NB + 1];     // 16 MB static scratch (allowed)

// --- bucket table build: table[t] = min{i : keys[i] >= (t<<SHIFT)} ---------
__global__ void build_table_kernel(const int* __restrict__ keys, int H) {
    int i = blockIdx.x * blockDim.x + threadIdx.x;
    if (i > H) return;
    int b0 = (i == 0) ? -1 : (keys[i - 1] >> SHIFT);
    int b1 = (i == H) ? NB : (keys[i] >> SHIFT);
    for (int t = b0 + 1; t <= b1; ++t) g_table[t] = i;
}

// spread low 8 bits of v to bit positions 0,3,6,...,21
__device__ __forceinline__ int spread3(int v) {
    v &= 0xFF;                        // matches ((v>>i)&1), i<8, incl. v=-1,256
    v = (v | (v << 8)) & 0x00F00F;
    v = (v | (v << 4)) & 0x0C30C3;
    v = (v | (v << 2)) & 0x249249;
    return v;
}

__global__ __launch_bounds__(256)
void interp_kernel(const float*  __restrict__ data,      // [H,32]
                   const float4* __restrict__ pts,       // [N] (x,y,z,b)
                   const int*    __restrict__ keys,      // [H] sorted
                   float*        __restrict__ out,       // [N,32]
                   int N, int H) {
    int n = blockIdx.x * blockDim.x + threadIdx.x;
    if (n >= N) return;

    float4 p = pts[n];

    // xf = (x + 1) * 128 - 0.5, explicitly unfused to match reference f32 ops
    float xf = __fadd_rn(__fmul_rn(__fadd_rn(p.x, 1.0f), 128.0f), -0.5f);
    float yf = __fadd_rn(__fmul_rn(__fadd_rn(p.y, 1.0f), 128.0f), -0.5f);
    float zf = __fadd_rn(__fmul_rn(__fadd_rn(p.z, 1.0f), 128.0f), -0.5f);

    float xfl = floorf(xf), yfl = floorf(yf), zfl = floorf(zf);
    float fx = __fsub_rn(xf, xfl);
    float fy = __fsub_rn(yf, yfl);
    float fz = __fsub_rn(zf, zfl);
    int xi = (int)xfl, yi = (int)yfl, zi = (int)zfl;

    int bb = ((int)p.w) << (3 * DEPTH);

    // Precompute spreads for both corner coordinates per axis
    int sx0 = spread3(xi)     << 2, sx1 = spread3(xi + 1) << 2;
    int sy0 = spread3(yi)     << 1, sy1 = spread3(yi + 1) << 1;
    int sz0 = spread3(zi),          sz1 = spread3(zi + 1);

    float wx0 = 1.0f - fx, wy0 = 1.0f - fy, wz0 = 1.0f - fz;

    int   key[8];
    float w[8];
    #pragma unroll
    for (int c = 0; c < 8; ++c) {
        int gx = (c >> 2) & 1, gy = (c >> 1) & 1, gz = c & 1;
        key[c] = bb | (gx ? sx1 : sx0) | (gy ? sy1 : sy0) | (gz ? sz1 : sz0);
        w[c]   = (gx ? fx : wx0) * (gy ? fy : wy0) * (gz ? fz : wz0);
    }

    // Phase 1: bucket ranges (16 independent loads -> good MLP)
    int lo[8], hi[8];
    #pragma unroll
    for (int c = 0; c < 8; ++c) {
        int t = key[c] >> SHIFT;
        lo[c] = g_table[t];
        hi[c] = g_table[t + 1];
    }

    // Phase 2: short lower_bound within bucket (avg < 1 probe)
    int  pos[8];
    bool val[8];
    #pragma unroll
    for (int c = 0; c < 8; ++c) {
        int l = lo[c], h = hi[c], h0 = h;
        while (l < h) {
            int m = (l + h) >> 1;
            if (keys[m] < key[c]) l = m + 1; else h = m;
        }
        pos[c] = l;
        // if l == h0, the bucket had no element >= key inside its range;
        // keys[l] (next bucket) is guaranteed > key -> invalid, no load.
        val[c] = (l < h0) && (keys[l] == key[c]);
    }

    // Phase 3: gather + accumulate (only ~3% of corners are valid)
    float4 acc[8];
    #pragma unroll
    for (int j = 0; j < 8; ++j) acc[j] = make_float4(0.f, 0.f, 0.f, 0.f);
    float wsum = 0.0f;

    #pragma unroll
    for (int c = 0; c < 8; ++c) {
        if (val[c] && w[c] != 0.0f) {
            wsum += w[c];
            const float4* row = (const float4*)(data + (size_t)pos[c] * 32);
            float wc = w[c];
            #pragma unroll
            for (int j = 0; j < 8; ++j) {
                float4 f = row[j];
                acc[j].x += wc * f.x;
                acc[j].y += wc * f.y;
                acc[j].z += wc * f.z;
                acc[j].w += wc * f.w;
            }
        }
    }

    float inv = 1.0f / (wsum + 1e-12f);
    float4* o = (float4*)(out + (size_t)n * 32);
    #pragma unroll
    for (int j = 0; j < 8; ++j) {
        float4 a = acc[j];
        a.x *= inv; a.y *= inv; a.z *= inv; a.w *= inv;
        o[j] = a;
    }
}

extern "C" void kernel_launch(void* const* d_in, const int* in_sizes, int n_in,
                              void* d_out, int out_size) {
    const float*  data = (const float*)d_in[0];
    const float4* pts  = (const float4*)d_in[1];
    const int*    keys = (const int*)d_in[2];
    // d_in[3] = depth (constant 8, hardcoded)

    int N = in_sizes[1] / 4;
    int H = in_sizes[2];

    build_table_kernel<<<(H + 1 + 255) / 256, 256>>>(keys, H);
    interp_kernel<<<(N + 255) / 256, 256>>>(data, pts, keys,
                                            (float*)d_out, N, H);
}

// round 3
// speedup vs baseline: 1.1295x; 1.1295x over previous
#include <cuda_runtime.h>

// ---------------------------------------------------------------------------
// OctreeInterp: trilinear interp over a sparse octree (depth=8, B=4).
// R2: occupancy-focused rework.
//   - bucket table keeps only lower bound; in-bucket search is a short
//     sentinel-guarded linear scan (avg ~1.25 key loads, no 'hi' load)
//   - 128-thread blocks + __launch_bounds__(128,8) to cap regs at 64
//   - zero fast path for points with no valid corner (~78%)
// ---------------------------------------------------------------------------

#define DEPTH      8
#define KEY_BITS   26               // 2 batch bits + 3*DEPTH morton bits
#define NB_LOG     22
#define NB         (1 << NB_LOG)    // 4,194,304 buckets
#define SHIFT      (KEY_BITS - NB_LOG)  // 4

__device__ int g_table[NB + 1];     // 16 MB static scratch

// table[t] = min{i : keys[i] >= (t<<SHIFT)}
__global__ void build_table_kernel(const int* __restrict__ keys, int H) {
    int i = blockIdx.x * blockDim.x + threadIdx.x;
    if (i > H) return;
    int b0 = (i == 0) ? -1 : (keys[i - 1] >> SHIFT);
    int b1 = (i == H) ? NB : (keys[i] >> SHIFT);
    for (int t = b0 + 1; t <= b1; ++t) g_table[t] = i;
}

// spread low 8 bits of v to bit positions 0,3,6,...,21
__device__ __forceinline__ int spread3(int v) {
    v &= 0xFF;                        // matches ((v>>i)&1) for i<8, incl. -1,256
    v = (v | (v << 8)) & 0x00F00F;
    v = (v | (v << 4)) & 0x0C30C3;
    v = (v | (v << 2)) & 0x249249;
    return v;
}

__global__ void __launch_bounds__(128, 8)
interp_kernel(const float*  __restrict__ data,      // [H,32]
              const float4* __restrict__ pts,       // [N] (x,y,z,b)
              const int*    __restrict__ keys,      // [H] sorted
              float*        __restrict__ out,       // [N,32]
              int N, int H) {
    int n = blockIdx.x * blockDim.x + threadIdx.x;
    if (n >= N) return;

    float4 p = pts[n];

    // xf = (x + 1) * 128 - 0.5, explicitly unfused to match reference f32 ops
    float xf = __fadd_rn(__fmul_rn(__fadd_rn(p.x, 1.0f), 128.0f), -0.5f);
    float yf = __fadd_rn(__fmul_rn(__fadd_rn(p.y, 1.0f), 128.0f), -0.5f);
    float zf = __fadd_rn(__fmul_rn(__fadd_rn(p.z, 1.0f), 128.0f), -0.5f);

    float xfl = floorf(xf), yfl = floorf(yf), zfl = floorf(zf);
    float fx = __fsub_rn(xf, xfl);
    float fy = __fsub_rn(yf, yfl);
    float fz = __fsub_rn(zf, zfl);
    int xi = (int)xfl, yi = (int)yfl, zi = (int)zfl;

    int bb = ((int)p.w) << (3 * DEPTH);

    int sx0 = spread3(xi)     << 2, sx1 = spread3(xi + 1) << 2;
    int sy0 = spread3(yi)     << 1, sy1 = spread3(yi + 1) << 1;
    int sz0 = spread3(zi),          sz1 = spread3(zi + 1);

    float wx0 = 1.0f - fx, wy0 = 1.0f - fy, wz0 = 1.0f - fz;

    int   key[8];
    float w[8];
    #pragma unroll
    for (int c = 0; c < 8; ++c) {
        int gx = (c >> 2) & 1, gy = (c >> 1) & 1, gz = c & 1;
        key[c] = bb | (gx ? sx1 : sx0) | (gy ? sy1 : sy0) | (gz ? sz1 : sz0);
        w[c]   = (gx ? fx : wx0) * (gy ? fy : wy0) * (gz ? fz : wz0);
    }

    // Phase 1: bucket lower bounds (8 independent L2 loads, good MLP)
    int pos[8];
    #pragma unroll
    for (int c = 0; c < 8; ++c)
        pos[c] = __ldg(&g_table[key[c] >> SHIFT]);

    // Phase 2: first key probe batched (8 independent loads), then a short
    // sentinel-guarded linear scan (bucket occupancy avg 0.5 -> rare).
    int cur[8];
    #pragma unroll
    for (int c = 0; c < 8; ++c)
        cur[c] = __ldg(&keys[min(pos[c], H - 1)]);

    unsigned vm = 0;
    #pragma unroll
    for (int c = 0; c < 8; ++c) {
        int pp = pos[c];
        int k  = (pp < H) ? cur[c] : 0x7fffffff;
        while (k < key[c]) {
            ++pp;
            k = (pp < H) ? __ldg(&keys[pp]) : 0x7fffffff;
        }
        pos[c] = pp;
        if (k == key[c]) vm |= (1u << c);
    }

    float4* o = (float4*)(out + (size_t)n * 32);

    // Zero fast path: no valid corner -> out = 0 / (0 + 1e-12) = 0
    if (vm == 0) {
        float4 z = make_float4(0.f, 0.f, 0.f, 0.f);
        #pragma unroll
        for (int j = 0; j < 8; ++j) o[j] = z;
        return;
    }

    // Phase 3: gather + accumulate over valid corners
    float4 acc[8];
    #pragma unroll
    for (int j = 0; j < 8; ++j) acc[j] = make_float4(0.f, 0.f, 0.f, 0.f);
    float wsum = 0.0f;

    #pragma unroll
    for (int c = 0; c < 8; ++c) {
        if (vm & (1u << c)) {
            float wc = w[c];
            wsum += wc;
            const float4* row = (const float4*)(data + (size_t)pos[c] * 32);
            #pragma unroll
            for (int j = 0; j < 8; ++j) {
                float4 f = __ldg(&row[j]);
                acc[j].x += wc * f.x;
                acc[j].y += wc * f.y;
                acc[j].z += wc * f.z;
                acc[j].w += wc * f.w;
            }
        }
    }

    float inv = 1.0f / (wsum + 1e-12f);
    #pragma unroll
    for (int j = 0; j < 8; ++j) {
        float4 a = acc[j];
        a.x *= inv; a.y *= inv; a.z *= inv; a.w *= inv;
        o[j] = a;
    }
}

extern "C" void kernel_launch(void* const* d_in, const int* in_sizes, int n_in,
                              void* d_out, int out_size) {
    const float*  data = (const float*)d_in[0];
    const float4* pts  = (const float4*)d_in[1];
    const int*    keys = (const int*)d_in[2];
    // d_in[3] = depth (constant 8, hardcoded)

    int N = in_sizes[1] / 4;
    int H = in_sizes[2];

    build_table_kernel<<<(H + 1 + 255) / 256, 256>>>(keys, H);
    interp_kernel<<<(N + 127) / 128, 128>>>(data, pts, keys,
                                            (float*)d_out, N, H);
}